// round 1
// baseline (speedup 1.0000x reference)
#include <cuda_runtime.h>
#include <cstdint>

#define NB   65536   // batch rows
#define DD   64      // feature dim
#define NE   16      // experts
#define NO   512     // output dim
#define CAP  4096    // max rows per expert-pair bucket (expected ~546, huge margin)
#define NPAIR 256    // pair id = a*16+b (a<b); 120 active

#define BM 64        // rows per GEMM tile
#define BN 128       // output cols per tile
#define BK 128       // concat K (two experts x D=64)

// ---------------- scratch (static __device__, no allocation) ----------------
__device__ int    g_cnt[NPAIR * 32];      // padded stride 32 ints (128B) to spread LTS slices
__device__ int    g_rows[NPAIR * CAP];
__device__ float2 g_gates[NPAIR * CAP];   // (gate_of_min_expert, gate_of_max_expert)

// ---------------- packed f32x2 helpers (Blackwell FFMA2) ----------------
__device__ __forceinline__ unsigned long long pk2(float lo, float hi) {
    unsigned long long r;
    asm("mov.b64 %0, {%1, %2};" : "=l"(r) : "f"(lo), "f"(hi));
    return r;
}
__device__ __forceinline__ void upk2(unsigned long long v, float& lo, float& hi) {
    asm("mov.b64 {%0, %1}, %2;" : "=f"(lo), "=f"(hi) : "l"(v));
}
__device__ __forceinline__ unsigned long long ffma2(unsigned long long a,
                                                    unsigned long long b,
                                                    unsigned long long c) {
    unsigned long long d;
    asm("fma.rn.f32x2 %0, %1, %2, %3;" : "=l"(d) : "l"(a), "l"(b), "l"(c));
    return d;
}

// ---------------- kernel 1: gating + pair bucketing ----------------
__global__ void moe_gating(const float* __restrict__ x,
                           const float* __restrict__ wg,
                           const float* __restrict__ bg) {
    __shared__ float wgs[DD * NE];
    __shared__ float bgs[NE];
    int t = threadIdx.x;
    for (int i = t; i < DD * NE; i += blockDim.x) wgs[i] = wg[i];
    if (t < NE) bgs[t] = bg[t];
    __syncthreads();

    int row = blockIdx.x * blockDim.x + t;
    const float4* xr = (const float4*)(x + (size_t)row * DD);

    float z[NE];
#pragma unroll
    for (int e = 0; e < NE; e++) z[e] = bgs[e];
#pragma unroll
    for (int k4 = 0; k4 < DD / 4; k4++) {
        float4 v = xr[k4];
#pragma unroll
        for (int e = 0; e < NE; e++) {
            z[e] += v.x * wgs[(k4 * 4 + 0) * NE + e]
                  + v.y * wgs[(k4 * 4 + 1) * NE + e]
                  + v.z * wgs[(k4 * 4 + 2) * NE + e]
                  + v.w * wgs[(k4 * 4 + 3) * NE + e];
        }
    }

    // top-2 (stable: first index wins ties, matching jax.lax.top_k)
    float v0 = -1e30f, v1 = -1e30f;
    int i0 = 0, i1 = 0;
#pragma unroll
    for (int e = 0; e < NE; e++) {
        float ze = z[e];
        if (ze > v0) { v1 = v0; i1 = i0; v0 = ze; i0 = e; }
        else if (ze > v1) { v1 = ze; i1 = e; }
    }

    // softmax probs of top-2 (full denominator), then top-k renorm (+1e-6)
    float s = 0.f;
#pragma unroll
    for (int e = 0; e < NE; e++) s += expf(z[e] - v0);
    float p0 = 1.0f / s;              // expf(0)/s
    float p1 = expf(v1 - v0) / s;
    float den = p0 + p1 + 1e-6f;
    float gate0 = p0 / den;
    float gate1 = p1 / den;

    int a, b; float ga, gb;
    if (i0 < i1) { a = i0; b = i1; ga = gate0; gb = gate1; }
    else         { a = i1; b = i0; ga = gate1; gb = gate0; }
    int p = a * NE + b;

    int pos = atomicAdd(&g_cnt[p * 32], 1);
    if (pos < CAP) {
        g_rows[p * CAP + pos]  = row;
        g_gates[p * CAP + pos] = make_float2(ga, gb);
    }
}

// ---------------- kernel 2: pair-bucket GEMM (no atomics, single write) ----------------
// y[r] = (g_a * x[r]) @ W_a + (g_b * x[r]) @ W_b + g_a*be_a + g_b*be_b
// as one K=128 GEMM with gates folded into the A operand.
__global__ __launch_bounds__(256, 2)
void moe_pair_gemm(const float* __restrict__ x,
                   const float* __restrict__ We,
                   const float* __restrict__ be,
                   float* __restrict__ y) {
    int p = blockIdx.z;
    int cn = g_cnt[p * 32];
    if (cn > CAP) cn = CAP;
    int r0 = blockIdx.x * BM;
    if (r0 >= cn) return;                 // empty tile / inactive pair: fast exit

    int a = p >> 4, b = p & 15;
    int o0 = blockIdx.y * BN;
    int t = threadIdx.x;

    extern __shared__ unsigned char smraw[];
    float*  xs   = (float*)smraw;             // [BK][BM]  transposed, gate-scaled
    float*  ws   = xs + BK * BM;              // [BK][BN]
    float*  besA = ws + BK * BN;              // [BN]
    float*  besB = besA + BN;                 // [BN]
    float2* gsh  = (float2*)(besB + BN);      // [BM]
    int*    rsh  = (int*)(gsh + BM);          // [BM]

    // row indices / gates / bias columns
    if (t < BM) {
        int idx = r0 + t;
        int row = (idx < cn) ? g_rows[p * CAP + idx] : -1;
        rsh[t] = row;
        gsh[t] = (idx < cn) ? g_gates[p * CAP + idx] : make_float2(0.f, 0.f);
    }
    if (t < BN) {
        besA[t] = be[a * NO + o0 + t];
        besB[t] = be[b * NO + o0 + t];
    }

    // xs fill: thread (r = t&63, kq = t>>6) loads 16 floats of row r, writes both
    // gate-scaled halves transposed. Consecutive lanes -> consecutive r: conflict-free STS.
    {
        int r = t & 63, kq = t >> 6;
        int idx = r0 + r;
        bool valid = (idx < cn);
        float2 g   = valid ? g_gates[p * CAP + idx] : make_float2(0.f, 0.f);
        int row    = valid ? g_rows[p * CAP + idx] : 0;
        const float4* xr = (const float4*)(x + (size_t)row * DD + kq * 16);
#pragma unroll
        for (int i = 0; i < 4; i++) {
            float4 v = xr[i];
            int k = kq * 16 + i * 4;
            xs[(k + 0) * BM + r]        = g.x * v.x;
            xs[(k + 1) * BM + r]        = g.x * v.y;
            xs[(k + 2) * BM + r]        = g.x * v.z;
            xs[(k + 3) * BM + r]        = g.x * v.w;
            xs[(k + 64) * BM + r]       = g.y * v.x;
            xs[(k + 65) * BM + r]       = g.y * v.y;
            xs[(k + 66) * BM + r]       = g.y * v.z;
            xs[(k + 67) * BM + r]       = g.y * v.w;
        }
    }

    // ws fill: [W_a ; W_b] column tile, fully coalesced float4 loads/stores
    {
        const float* Wa = We + (size_t)a * DD * NO + o0;
        const float* Wb = We + (size_t)b * DD * NO + o0;
#pragma unroll
        for (int i = 0; i < 16; i++) {
            int fi = t + 256 * i;         // 0..4095 float4 slots
            int n4 = fi & 31;
            int kk = fi >> 5;             // 0..127
            const float* src = (kk < 64) ? (Wa + kk * NO + n4 * 4)
                                         : (Wb + (kk - 64) * NO + n4 * 4);
            float4 v = *(const float4*)src;
            *(float4*)&ws[kk * BN + n4 * 4] = v;
        }
    }
    __syncthreads();

    // main loop: 4 rows x 8 cols per thread, packed f32x2 over row pairs
    int tx = t & 15, ty = t >> 4;
    unsigned long long acc[2][2][4];       // [rowpair][colgroup][col]
#pragma unroll
    for (int pp = 0; pp < 2; pp++)
#pragma unroll
        for (int j = 0; j < 2; j++)
#pragma unroll
            for (int c = 0; c < 4; c++) acc[pp][j][c] = 0ULL;

#pragma unroll 4
    for (int k = 0; k < BK; k++) {
        float4 av = *(const float4*)&xs[k * BM + 4 * ty];
        unsigned long long a01 = pk2(av.x, av.y);
        unsigned long long a23 = pk2(av.z, av.w);
        float4 b0 = *(const float4*)&ws[k * BN + 4 * tx];
        float4 b1 = *(const float4*)&ws[k * BN + 64 + 4 * tx];

        unsigned long long bb;
        bb = pk2(b0.x, b0.x); acc[0][0][0] = ffma2(a01, bb, acc[0][0][0]); acc[1][0][0] = ffma2(a23, bb, acc[1][0][0]);
        bb = pk2(b0.y, b0.y); acc[0][0][1] = ffma2(a01, bb, acc[0][0][1]); acc[1][0][1] = ffma2(a23, bb, acc[1][0][1]);
        bb = pk2(b0.z, b0.z); acc[0][0][2] = ffma2(a01, bb, acc[0][0][2]); acc[1][0][2] = ffma2(a23, bb, acc[1][0][2]);
        bb = pk2(b0.w, b0.w); acc[0][0][3] = ffma2(a01, bb, acc[0][0][3]); acc[1][0][3] = ffma2(a23, bb, acc[1][0][3]);
        bb = pk2(b1.x, b1.x); acc[0][1][0] = ffma2(a01, bb, acc[0][1][0]); acc[1][1][0] = ffma2(a23, bb, acc[1][1][0]);
        bb = pk2(b1.y, b1.y); acc[0][1][1] = ffma2(a01, bb, acc[0][1][1]); acc[1][1][1] = ffma2(a23, bb, acc[1][1][1]);
        bb = pk2(b1.z, b1.z); acc[0][1][2] = ffma2(a01, bb, acc[0][1][2]); acc[1][1][2] = ffma2(a23, bb, acc[1][1][2]);
        bb = pk2(b1.w, b1.w); acc[0][1][3] = ffma2(a01, bb, acc[0][1][3]); acc[1][1][3] = ffma2(a23, bb, acc[1][1][3]);
    }

    // epilogue: add gated biases, single STG.128 per (row, colgroup)
#pragma unroll
    for (int mi = 0; mi < 4; mi++) {
        int m = 4 * ty + mi;
        int row = rsh[m];
        if (row < 0) continue;
        float2 g = gsh[m];
#pragma unroll
        for (int j = 0; j < 2; j++) {
            float4 outv;
            float* ov = &outv.x;
#pragma unroll
            for (int c = 0; c < 4; c++) {
                float lo, hi;
                upk2(acc[mi >> 1][j][c], lo, hi);
                float v = (mi & 1) ? hi : lo;
                int n = 4 * tx + 64 * j + c;
                ov[c] = v + g.x * besA[n] + g.y * besB[n];
            }
            *(float4*)&y[(size_t)row * NO + o0 + 4 * tx + 64 * j] = outv;
        }
    }
}

// ---------------- launch ----------------
extern "C" void kernel_launch(void* const* d_in, const int* in_sizes, int n_in,
                              void* d_out, int out_size) {
    const float* x  = (const float*)d_in[0];
    const float* wg = (const float*)d_in[1];
    const float* bg = (const float*)d_in[2];
    const float* We = (const float*)d_in[3];
    const float* be = (const float*)d_in[4];
    float* y = (float*)d_out;

    // zero bucket counters (graph-capturable memset node)
    void* cntPtr = nullptr;
    cudaGetSymbolAddress(&cntPtr, g_cnt);
    cudaMemsetAsync(cntPtr, 0, sizeof(int) * NPAIR * 32);

    moe_gating<<<NB / 256, 256>>>(x, wg, bg);

    constexpr size_t SMEM = (size_t)(BK * BM + BK * BN + 2 * BN) * 4
                          + BM * sizeof(float2) + BM * sizeof(int);
    cudaFuncSetAttribute(moe_pair_gemm,
                         cudaFuncAttributeMaxDynamicSharedMemorySize, (int)SMEM);
    dim3 grid(CAP / BM, NO / BN, NPAIR);
    moe_pair_gemm<<<grid, 256, SMEM>>>(x, We, be, y);
}

// round 6
// speedup vs baseline: 2.2578x; 2.2578x over previous
#include <cuda_runtime.h>
#include <cstdint>

#define NB    65536
#define DD    64
#define NE    16
#define NO    512
#define CAP   4096
#define NPAIR 256
#define BM    128
#define BN    128
#define MAXT  1024

#define XS_STRIDE 68    // floats per A row (64 + 4 pad): conflict-free frag LDS
#define WS_STRIDE 132   // floats per B row (128 + 4 pad)

// ---- smem layout (floats/bytes) ----
#define SM_XS   0                                   // 128 x 68 floats = 34816 B
#define SM_WS   (128 * XS_STRIDE * 4)               // 128 x 132 floats = 67584 B
#define SM_BESA (SM_WS + 128 * WS_STRIDE * 4)       // 512 B
#define SM_BESB (SM_BESA + 512)                     // 512 B
#define SM_G    (SM_BESB + 512)                     // float2[128] = 1024 B
#define SM_R    (SM_G + 1024)                       // int[128]   = 512 B
#define SMEM_TOTAL (SM_R + 512)

// ---- scratch ----
__device__ int    g_cnt[NPAIR * 32];
__device__ int    g_rows[NPAIR * CAP];
__device__ float2 g_gates[NPAIR * CAP];
__device__ int    g_ntiles;
__device__ int2   g_tiles[MAXT];

// ---- helpers ----
__device__ __forceinline__ uint32_t tf32c(float f) {
    uint32_t r; asm("cvt.rna.tf32.f32 %0, %1;" : "=r"(r) : "f"(f)); return r;
}
__device__ __forceinline__ void mma8(float* d, const uint32_t* a, uint32_t b0, uint32_t b1) {
    asm volatile(
        "mma.sync.aligned.m16n8k8.row.col.f32.tf32.tf32.f32 "
        "{%0,%1,%2,%3}, {%4,%5,%6,%7}, {%8,%9}, {%0,%1,%2,%3};"
        : "+f"(d[0]), "+f"(d[1]), "+f"(d[2]), "+f"(d[3])
        : "r"(a[0]), "r"(a[1]), "r"(a[2]), "r"(a[3]), "r"(b0), "r"(b1));
}

// ---------------- kernel 1: gating + pair bucketing ----------------
__global__ void moe_gating(const float* __restrict__ x,
                           const float* __restrict__ wg,
                           const float* __restrict__ bg) {
    __shared__ float wgs[DD * NE];
    __shared__ float bgs[NE];
    int t = threadIdx.x;
    for (int i = t; i < DD * NE; i += blockDim.x) wgs[i] = wg[i];
    if (t < NE) bgs[t] = bg[t];
    __syncthreads();

    int row = blockIdx.x * blockDim.x + t;
    const float4* xr = (const float4*)(x + (size_t)row * DD);

    float z[NE];
#pragma unroll
    for (int e = 0; e < NE; e++) z[e] = bgs[e];
#pragma unroll
    for (int k4 = 0; k4 < DD / 4; k4++) {
        float4 v = xr[k4];
#pragma unroll
        for (int e = 0; e < NE; e++) {
            z[e] += v.x * wgs[(k4 * 4 + 0) * NE + e]
                  + v.y * wgs[(k4 * 4 + 1) * NE + e]
                  + v.z * wgs[(k4 * 4 + 2) * NE + e]
                  + v.w * wgs[(k4 * 4 + 3) * NE + e];
        }
    }
    float v0 = -1e30f, v1 = -1e30f;
    int i0 = 0, i1 = 0;
#pragma unroll
    for (int e = 0; e < NE; e++) {
        float ze = z[e];
        if (ze > v0) { v1 = v0; i1 = i0; v0 = ze; i0 = e; }
        else if (ze > v1) { v1 = ze; i1 = e; }
    }
    float s = 0.f;
#pragma unroll
    for (int e = 0; e < NE; e++) s += expf(z[e] - v0);
    float p0 = 1.0f / s;
    float p1 = expf(v1 - v0) / s;
    float den = p0 + p1 + 1e-6f;
    float gate0 = p0 / den, gate1 = p1 / den;

    int a, b; float ga, gb;
    if (i0 < i1) { a = i0; b = i1; ga = gate0; gb = gate1; }
    else         { a = i1; b = i0; ga = gate1; gb = gate0; }
    int p = a * NE + b;

    int pos = atomicAdd(&g_cnt[p * 32], 1);
    if (pos < CAP) {
        g_rows[p * CAP + pos]  = row;
        g_gates[p * CAP + pos] = make_float2(ga, gb);
    }
}

// ---------------- kernel 1b: compact tile work queue ----------------
__global__ void build_tiles() {
    int p = threadIdx.x;
    if (p == 0) g_ntiles = 0;
    __syncthreads();
    int cn = g_cnt[p * 32];
    if (cn > CAP) cn = CAP;
    int nt = (cn + BM - 1) / BM;
    if (nt > 0) {
        int base = atomicAdd(&g_ntiles, nt);
        for (int i = 0; i < nt; i++)
            if (base + i < MAXT) g_tiles[base + i] = make_int2(p, i * BM);
    }
}

// ---------------- kernel 2: pair-bucket GEMM via mma.sync tf32 ----------------
// y[rows] = gatherA(x, gates) @ [Wa ; Wb] + gated bias, one store per output.
// Warp grid 4x2: warp wm in [0,4) owns 32 rows, wn in [0,2) owns 64 cols.
__global__ __launch_bounds__(256, 2)
void moe_pair_gemm(const float* __restrict__ x,
                   const float* __restrict__ We,
                   const float* __restrict__ be,
                   float* __restrict__ y) {
    int ti = blockIdx.x;
    if (ti >= g_ntiles) return;
    int2 te = g_tiles[ti];
    int p = te.x, r0 = te.y;
    int cn = g_cnt[p * 32];
    if (cn > CAP) cn = CAP;
    int ea = p >> 4, eb = p & 15;
    int o0 = blockIdx.y * BN;
    int t = threadIdx.x, wid = t >> 5, lane = t & 31;
    int wm = wid & 3, wn = wid >> 2;
    int qid = lane >> 2, qtid = lane & 3;   // groupID / threadID_in_group

    extern __shared__ unsigned char sm[];
    float*    xs  = (float*)(sm + SM_XS);
    uint32_t* ws  = (uint32_t*)(sm + SM_WS);
    float*    bA  = (float*)(sm + SM_BESA);
    float*    bB  = (float*)(sm + SM_BESB);
    float2*   gsh = (float2*)(sm + SM_G);
    int*      rsh = (int*)(sm + SM_R);

    // rows / gates / bias
    if (t < 128) {
        int idx = r0 + t;
        bool v = idx < cn;
        rsh[t] = v ? g_rows[p * CAP + idx] : -1;
        gsh[t] = v ? g_gates[p * CAP + idx] : make_float2(0.f, 0.f);
        bA[t] = be[(size_t)ea * NO + o0 + t];
        bB[t] = be[(size_t)eb * NO + o0 + t];
    }

    // A fill: raw (ungated) x rows, [128][64] pad-68
    {
        int r = t & 127, h = t >> 7;        // h: k-half 0..31 / 32..63
        int idx = r0 + r;
        int row = (idx < cn) ? g_rows[p * CAP + idx] : 0;
        const float4* xr = (const float4*)(x + (size_t)row * DD + h * 32);
        float* dst = xs + r * XS_STRIDE + h * 32;
#pragma unroll
        for (int q = 0; q < 8; q++) *(float4*)(dst + 4 * q) = xr[q];
    }

    // B fill: [Wa ; Wb] as [k][n], tf32-rounded, pad-132
    {
        const float* Wa = We + (size_t)ea * DD * NO + o0;
        const float* Wb = We + (size_t)eb * DD * NO + o0;
#pragma unroll
        for (int i = 0; i < 16; i++) {
            int fi = t + 256 * i;           // 0..4095 float4 slots
            int n4 = fi & 31;               // col/4
            int k  = fi >> 5;               // 0..127
            const float* src = ((k < 64) ? (Wa + (size_t)k * NO)
                                         : (Wb + (size_t)(k - 64) * NO)) + 4 * n4;
            float4 v = *(const float4*)src;
            uint4 u = make_uint4(tf32c(v.x), tf32c(v.y), tf32c(v.z), tf32c(v.w));
            *(uint4*)(ws + k * WS_STRIDE + 4 * n4) = u;
        }
    }
    __syncthreads();

    // per-thread row gates + row ids (rows: wm*32 + mt*16 + qid (+8))
    float2 G[2][2];
    int    R[2][2];
#pragma unroll
    for (int mt = 0; mt < 2; mt++)
#pragma unroll
        for (int j = 0; j < 2; j++) {
            int m = wm * 32 + mt * 16 + j * 8 + qid;
            G[mt][j] = gsh[m];
            R[mt][j] = rsh[m];
        }

    float acc[2][8][4];
#pragma unroll
    for (int mt = 0; mt < 2; mt++)
#pragma unroll
        for (int nt = 0; nt < 8; nt++)
#pragma unroll
            for (int c = 0; c < 4; c++) acc[mt][nt][c] = 0.f;

    // main loop: 2 expert halves x 8 k8-steps
#pragma unroll
    for (int h = 0; h < 2; h++) {
        // gate per (mt, row-half) for this expert half
        float gh[2][2];
#pragma unroll
        for (int mt = 0; mt < 2; mt++)
#pragma unroll
            for (int j = 0; j < 2; j++)
                gh[mt][j] = h ? G[mt][j].y : G[mt][j].x;

#pragma unroll
        for (int ks = 0; ks < 8; ks++) {
            int ka = ks * 8 + qtid;              // col in xs (0..63)
            uint32_t afr[2][4];
#pragma unroll
            for (int mt = 0; mt < 2; mt++) {
                const float* ar = xs + (wm * 32 + mt * 16 + qid) * XS_STRIDE + ka;
                afr[mt][0] = __float_as_uint(gh[mt][0] * ar[0]);
                afr[mt][1] = __float_as_uint(gh[mt][1] * ar[8 * XS_STRIDE]);
                afr[mt][2] = __float_as_uint(gh[mt][0] * ar[4]);
                afr[mt][3] = __float_as_uint(gh[mt][1] * ar[8 * XS_STRIDE + 4]);
            }
            int kb = h * 64 + ks * 8 + qtid;     // row in ws (0..127)
            const uint32_t* br = ws + kb * WS_STRIDE + wn * 64 + qid;
#pragma unroll
            for (int nt = 0; nt < 8; nt++) {
                uint32_t b0 = br[nt * 8];
                uint32_t b1 = br[4 * WS_STRIDE + nt * 8];
                mma8(acc[0][nt], afr[0], b0, b1);
                mma8(acc[1][nt], afr[1], b0, b1);
            }
        }
    }

    // epilogue: gated bias + direct scatter stores (each row written once)
#pragma unroll
    for (int mt = 0; mt < 2; mt++) {
#pragma unroll
        for (int j = 0; j < 2; j++) {
            int row = R[mt][j];
            if (row < 0) continue;
            float2 g = G[mt][j];
            float* yp = y + (size_t)row * NO + o0;
#pragma unroll
            for (int nt = 0; nt < 8; nt++) {
                int col = wn * 64 + nt * 8 + 2 * qtid;
                float2 ba = *(float2*)(bA + col);
                float2 bb = *(float2*)(bB + col);
                float2 o;
                o.x = acc[mt][nt][2 * j + 0] + g.x * ba.x + g.y * bb.x;
                o.y = acc[mt][nt][2 * j + 1] + g.x * ba.y + g.y * bb.y;
                *(float2*)(yp + col) = o;
            }
        }
    }
}

// ---------------- launch ----------------
extern "C" void kernel_launch(void* const* d_in, const int* in_sizes, int n_in,
                              void* d_out, int out_size) {
    const float* x  = (const float*)d_in[0];
    const float* wg = (const float*)d_in[1];
    const float* bg = (const float*)d_in[2];
    const float* We = (const float*)d_in[3];
    const float* be = (const float*)d_in[4];
    float* y = (float*)d_out;

    void* cntPtr = nullptr;
    cudaGetSymbolAddress(&cntPtr, g_cnt);
    cudaMemsetAsync(cntPtr, 0, sizeof(int) * NPAIR * 32);

    moe_gating<<<NB / 256, 256>>>(x, wg, bg);
    build_tiles<<<1, 256>>>();

    cudaFuncSetAttribute(moe_pair_gemm,
                         cudaFuncAttributeMaxDynamicSharedMemorySize, SMEM_TOTAL);
    dim3 grid(768, NO / BN, 1);
    moe_pair_gemm<<<grid, 256, SMEM_TOTAL>>>(x, We, be, y);
}

// round 7
// speedup vs baseline: 2.5758x; 1.1408x over previous
#include <cuda_runtime.h>
#include <cuda_fp16.h>
#include <cstdint>

#define NB    65536
#define DD    64
#define NE    16
#define NO    512
#define CAP   4096
#define NPAIR 256
#define BM    128
#define BN    128
#define MAXT  1024

#define AS 136   // halves per A row (128 + 8 pad) -> 272B row stride
#define BS 136   // halves per B row

// ---- smem layout (bytes) ----
#define SM_A    0                          // 128 x 136 halves = 34816 B
#define SM_B    34816                      // 128 x 136 halves = 34816 B
#define SM_BESA 69632                      // 512 B
#define SM_BESB 70144                      // 512 B
#define SM_G    70656                      // float2[128] = 1024 B
#define SM_R    71680                      // int[128] = 512 B
#define SMEM_TOTAL 72192

// ---- scratch ----
__device__ int    g_cnt[NPAIR * 32];
__device__ int    g_rows[NPAIR * CAP];
__device__ float2 g_gates[NPAIR * CAP];
__device__ int    g_ntiles;
__device__ int4   g_tiles[MAXT];           // {pair, r0, cn, 0}
__device__ int    g_done;

// ---- helpers ----
__device__ __forceinline__ uint32_t su32(const void* p) {
    uint32_t a;
    asm("{ .reg .u64 t; cvta.to.shared.u64 t, %1; cvt.u32.u64 %0, t; }" : "=r"(a) : "l"(p));
    return a;
}
__device__ __forceinline__ uint32_t packh2(float hi, float lo) {
    uint32_t r; asm("cvt.rn.f16x2.f32 %0, %1, %2;" : "=r"(r) : "f"(hi), "f"(lo)); return r;
}
__device__ __forceinline__ void ldx4(uint32_t* r, uint32_t addr) {
    asm volatile("ldmatrix.sync.aligned.m8n8.x4.shared.b16 {%0,%1,%2,%3}, [%4];"
                 : "=r"(r[0]), "=r"(r[1]), "=r"(r[2]), "=r"(r[3]) : "r"(addr));
}
__device__ __forceinline__ void ldx4t(uint32_t* r, uint32_t addr) {
    asm volatile("ldmatrix.sync.aligned.m8n8.x4.trans.shared.b16 {%0,%1,%2,%3}, [%4];"
                 : "=r"(r[0]), "=r"(r[1]), "=r"(r[2]), "=r"(r[3]) : "r"(addr));
}
__device__ __forceinline__ void mma16(float* d, const uint32_t* a, uint32_t b0, uint32_t b1) {
    asm volatile(
        "mma.sync.aligned.m16n8k16.row.col.f32.f16.f16.f32 "
        "{%0,%1,%2,%3}, {%4,%5,%6,%7}, {%8,%9}, {%0,%1,%2,%3};"
        : "+f"(d[0]), "+f"(d[1]), "+f"(d[2]), "+f"(d[3])
        : "r"(a[0]), "r"(a[1]), "r"(a[2]), "r"(a[3]), "r"(b0), "r"(b1));
}

// ---------------- kernel 1: gating + bucketing + fused tile build ----------------
__global__ void moe_gating(const float* __restrict__ x,
                           const float* __restrict__ wg,
                           const float* __restrict__ bg) {
    __shared__ float wgs[DD * NE];
    __shared__ float bgs[NE];
    __shared__ int   s_last, s_total;
    int t = threadIdx.x;
    for (int i = t; i < DD * NE; i += blockDim.x) wgs[i] = wg[i];
    if (t < NE) bgs[t] = bg[t];
    __syncthreads();

    int row = blockIdx.x * blockDim.x + t;
    const float4* xr = (const float4*)(x + (size_t)row * DD);
    const float4* wgs4 = (const float4*)wgs;

    float z[NE];
#pragma unroll
    for (int e = 0; e < NE; e++) z[e] = bgs[e];
#pragma unroll
    for (int k4 = 0; k4 < DD / 4; k4++) {
        float4 xv = xr[k4];
        const float* xc = &xv.x;
#pragma unroll
        for (int kk = 0; kk < 4; kk++) {
            float xk = xc[kk];
            int kb = (k4 * 4 + kk) * 4;
            float4 w0 = wgs4[kb + 0], w1 = wgs4[kb + 1], w2 = wgs4[kb + 2], w3 = wgs4[kb + 3];
            z[0]  += xk * w0.x; z[1]  += xk * w0.y; z[2]  += xk * w0.z; z[3]  += xk * w0.w;
            z[4]  += xk * w1.x; z[5]  += xk * w1.y; z[6]  += xk * w1.z; z[7]  += xk * w1.w;
            z[8]  += xk * w2.x; z[9]  += xk * w2.y; z[10] += xk * w2.z; z[11] += xk * w2.w;
            z[12] += xk * w3.x; z[13] += xk * w3.y; z[14] += xk * w3.z; z[15] += xk * w3.w;
        }
    }
    float v0 = -1e30f, v1 = -1e30f;
    int i0 = 0, i1 = 0;
#pragma unroll
    for (int e = 0; e < NE; e++) {
        float ze = z[e];
        if (ze > v0) { v1 = v0; i1 = i0; v0 = ze; i0 = e; }
        else if (ze > v1) { v1 = ze; i1 = e; }
    }
    float s = 0.f;
#pragma unroll
    for (int e = 0; e < NE; e++) s += __expf(z[e] - v0);
    float p0 = 1.0f / s;
    float p1 = __expf(v1 - v0) / s;
    float den = p0 + p1 + 1e-6f;
    float gate0 = p0 / den, gate1 = p1 / den;

    int a, b; float ga, gb;
    if (i0 < i1) { a = i0; b = i1; ga = gate0; gb = gate1; }
    else         { a = i1; b = i0; ga = gate1; gb = gate0; }
    int p = a * NE + b;

    int pos = atomicAdd(&g_cnt[p * 32], 1);
    if (pos < CAP) {
        g_rows[p * CAP + pos]  = row;
        g_gates[p * CAP + pos] = make_float2(ga, gb);
    }

    // ---- last-block fused tile build (removes build_tiles + memset launches) ----
    __syncthreads();
    if (t == 0) {
        __threadfence();
        s_last = (atomicAdd(&g_done, 1) == gridDim.x - 1) ? 1 : 0;
        s_total = 0;
    }
    __syncthreads();
    if (s_last) {
        __threadfence();
        int pp = t;                              // 256 threads = 256 pairs
        int cn = atomicAdd(&g_cnt[pp * 32], 0);  // atomic read (bypass L1)
        if (cn > CAP) cn = CAP;
        int nt = (cn + BM - 1) >> 7;
        if (nt > 0) {
            int base = atomicAdd(&s_total, nt);
            for (int i = 0; i < nt; i++)
                if (base + i < MAXT) g_tiles[base + i] = make_int4(pp, i * BM, cn, 0);
        }
        g_cnt[pp * 32] = 0;                      // self-reset for next replay
        __syncthreads();
        if (t == 0) { g_ntiles = s_total; g_done = 0; __threadfence(); }
    }
}

// ---------------- kernel 2: fp16 pair-bucket GEMM (ldmatrix + mma.sync) ----------------
// A[128][128] fp16 = [g_a*x | g_b*x] (gates folded), B[128][128] fp16 = [Wa ; Wb].
// Warp grid 4x2: warp (wm, wn) owns 32 rows x 64 cols. fp32 accumulate.
__global__ __launch_bounds__(256, 2)
void moe_pair_gemm(const float* __restrict__ x,
                   const float* __restrict__ We,
                   const float* __restrict__ be,
                   float* __restrict__ y) {
    int ti = blockIdx.x;
    if (ti >= g_ntiles) return;
    int4 te = g_tiles[ti];
    int p = te.x, r0 = te.y, cn = te.z;
    int ea = p >> 4, eb = p & 15;
    int o0 = blockIdx.y * BN;
    int t = threadIdx.x, wid = t >> 5, lane = t & 31;
    int wm = wid & 3, wn = wid >> 2;
    int qid = lane >> 2, qtid = lane & 3;
    int sub = lane >> 3, lr = lane & 7;

    extern __shared__ unsigned char sm[];
    uint32_t smb = su32(sm);
    __half* as = (__half*)(sm + SM_A);
    __half* bs = (__half*)(sm + SM_B);
    float*  bA = (float*)(sm + SM_BESA);
    float*  bB = (float*)(sm + SM_BESB);
    float2* gsh = (float2*)(sm + SM_G);
    int*    rsh = (int*)(sm + SM_R);

    // metadata
    if (t < 128) {
        int idx = r0 + t;
        bool v = idx < cn;
        rsh[t] = v ? g_rows[p * CAP + idx] : -1;
        gsh[t] = v ? g_gates[p * CAP + idx] : make_float2(0.f, 0.f);
        bA[t] = be[(size_t)ea * NO + o0 + t];
        bB[t] = be[(size_t)eb * NO + o0 + t];
    }

    // ---- A fill: gate-scaled fp16, both halves ----
    {
        int r = t & 127, h = t >> 7;           // h=0: g.x half (k 0..63), h=1: g.y half
        int idx = r0 + r;
        bool vld = idx < cn;
        float2 gg = vld ? g_gates[p * CAP + idx] : make_float2(0.f, 0.f);
        float g = h ? gg.y : gg.x;
        int row = vld ? g_rows[p * CAP + idx] : 0;
        const float4* xrp = (const float4*)(x + (size_t)row * DD);
        __half* dst = as + r * AS + h * 64;
#pragma unroll
        for (int s = 0; s < 8; s++) {
            float4 v = xrp[2 * s], w = xrp[2 * s + 1];
            uint4 u;
            u.x = packh2(g * v.y, g * v.x);
            u.y = packh2(g * v.w, g * v.z);
            u.z = packh2(g * w.y, g * w.x);
            u.w = packh2(g * w.w, g * w.z);
            *(uint4*)(dst + 8 * s) = u;
        }
    }

    // ---- B fill: [Wa ; Wb] rows k, fp16 ----
    {
        const float* Wa = We + (size_t)ea * DD * NO + o0;
        const float* Wb = We + (size_t)eb * DD * NO + o0;
#pragma unroll
        for (int i = 0; i < 8; i++) {
            int slot = t + 256 * i;            // 0..2047
            int n8 = slot & 15;                // 8-half group
            int k  = slot >> 4;                // 0..127
            const float* src = ((k < 64) ? (Wa + (size_t)k * NO)
                                         : (Wb + (size_t)(k - 64) * NO)) + 8 * n8;
            float4 v = *(const float4*)src;
            float4 w = *(const float4*)(src + 4);
            uint4 u;
            u.x = packh2(v.y, v.x);
            u.y = packh2(v.w, v.z);
            u.z = packh2(w.y, w.x);
            u.w = packh2(w.w, w.z);
            *(uint4*)(bs + k * BS + 8 * n8) = u;
        }
    }
    __syncthreads();

    // per-thread row metadata
    float2 G[2][2]; int R[2][2];
#pragma unroll
    for (int mt = 0; mt < 2; mt++)
#pragma unroll
        for (int j = 0; j < 2; j++) {
            int m = wm * 32 + mt * 16 + j * 8 + qid;
            G[mt][j] = gsh[m];
            R[mt][j] = rsh[m];
        }

    float acc[2][8][4];
#pragma unroll
    for (int mt = 0; mt < 2; mt++)
#pragma unroll
        for (int nt = 0; nt < 8; nt++)
#pragma unroll
            for (int c = 0; c < 4; c++) acc[mt][nt][c] = 0.f;

    // ldmatrix lane addresses
    uint32_t aadr[2], badr[4];
#pragma unroll
    for (int mt = 0; mt < 2; mt++) {
        int arow = wm * 32 + mt * 16 + (sub & 1) * 8 + lr;
        int acol = (sub >> 1) * 8;
        aadr[mt] = smb + SM_A + (uint32_t)(arow * AS + acol) * 2;
    }
#pragma unroll
    for (int pr = 0; pr < 4; pr++) {
        int brow = (sub & 1) * 8 + lr;
        int bcol = wn * 64 + pr * 16 + (sub >> 1) * 8;
        badr[pr] = smb + SM_B + (uint32_t)(brow * BS + bcol) * 2;
    }

    // main loop: 8 k16-steps
#pragma unroll
    for (int ks = 0; ks < 8; ks++) {
        uint32_t a0[4], a1[4], bb[4][4];
        ldx4(a0, aadr[0] + ks * 32);
        ldx4(a1, aadr[1] + ks * 32);
#pragma unroll
        for (int pr = 0; pr < 4; pr++) ldx4t(bb[pr], badr[pr] + ks * 16 * BS * 2);
#pragma unroll
        for (int nt = 0; nt < 8; nt++) {
            uint32_t b0 = bb[nt >> 1][(nt & 1) * 2];
            uint32_t b1 = bb[nt >> 1][(nt & 1) * 2 + 1];
            mma16(acc[0][nt], a0, b0, b1);
            mma16(acc[1][nt], a1, b0, b1);
        }
    }

    // epilogue: gated bias + one store per output element
#pragma unroll
    for (int mt = 0; mt < 2; mt++) {
#pragma unroll
        for (int j = 0; j < 2; j++) {
            int row = R[mt][j];
            if (row < 0) continue;
            float2 g = G[mt][j];
            float* yp = y + (size_t)row * NO + o0;
#pragma unroll
            for (int nt = 0; nt < 8; nt++) {
                int col = wn * 64 + nt * 8 + 2 * qtid;
                float2 ba = *(float2*)(bA + col);
                float2 bb2 = *(float2*)(bB + col);
                float2 o;
                o.x = acc[mt][nt][2 * j + 0] + g.x * ba.x + g.y * bb2.x;
                o.y = acc[mt][nt][2 * j + 1] + g.x * ba.y + g.y * bb2.y;
                *(float2*)(yp + col) = o;
            }
        }
    }
}

// ---------------- launch: exactly 2 kernels ----------------
extern "C" void kernel_launch(void* const* d_in, const int* in_sizes, int n_in,
                              void* d_out, int out_size) {
    const float* x  = (const float*)d_in[0];
    const float* wg = (const float*)d_in[1];
    const float* bg = (const float*)d_in[2];
    const float* We = (const float*)d_in[3];
    const float* be = (const float*)d_in[4];
    float* y = (float*)d_out;

    moe_gating<<<NB / 256, 256>>>(x, wg, bg);

    cudaFuncSetAttribute(moe_pair_gemm,
                         cudaFuncAttributeMaxDynamicSharedMemorySize, SMEM_TOTAL);
    dim3 grid(768, NO / BN, 1);
    moe_pair_gemm<<<grid, 256, SMEM_TOTAL>>>(x, We, be, y);
}

// round 11
// speedup vs baseline: 3.5458x; 1.3766x over previous
#include <cuda_runtime.h>
#include <cuda_fp16.h>
#include <cstdint>

#define NB    65536
#define DD    64
#define NE    16
#define NO    512
#define CAP   4096
#define NPAIR 256
#define BM    128
#define BN    128
#define MAXT  1024

#define AS 136   // halves per A row (128 + 8 pad) -> 272B row stride
#define BS 136   // halves per B row

// ---- smem layout (bytes) ----
#define SM_A    0                          // 128 x 136 halves = 34816 B
#define SM_B    34816                      // 128 x 136 halves = 34816 B
#define SM_BESA 69632                      // 512 B
#define SM_BESB 70144                      // 512 B
#define SM_G    70656                      // float2[128] = 1024 B
#define SM_R    71680                      // int[128] = 512 B
#define SMEM_TOTAL 72192

// ---- scratch ----
__device__ int    g_cnt[NPAIR * 32];
__device__ int    g_rows[NPAIR * CAP];
__device__ float2 g_gates[NPAIR * CAP];
__device__ int    g_ntiles;
__device__ int4   g_tiles[MAXT];           // {pair, r0, cn, 0}
__device__ int    g_done;
__device__ __half x16[(size_t)NB * DD];    // fp16 copy of x (written by gating)
__device__ __half We16[(size_t)NE * DD * NO];

// ---- helpers ----
__device__ __forceinline__ uint32_t su32(const void* p) {
    uint32_t a;
    asm("{ .reg .u64 t; cvta.to.shared.u64 t, %1; cvt.u32.u64 %0, t; }" : "=r"(a) : "l"(p));
    return a;
}
__device__ __forceinline__ uint32_t packh2(float hi, float lo) {
    uint32_t r; asm("cvt.rn.f16x2.f32 %0, %1, %2;" : "=r"(r) : "f"(hi), "f"(lo)); return r;
}
__device__ __forceinline__ uint32_t h2m(uint32_t a, __half2 g) {
    __half2 r = __hmul2(*(__half2*)&a, g);
    return *(uint32_t*)&r;
}
__device__ __forceinline__ void ldx4(uint32_t* r, uint32_t addr) {
    asm volatile("ldmatrix.sync.aligned.m8n8.x4.shared.b16 {%0,%1,%2,%3}, [%4];"
                 : "=r"(r[0]), "=r"(r[1]), "=r"(r[2]), "=r"(r[3]) : "r"(addr));
}
__device__ __forceinline__ void ldx4t(uint32_t* r, uint32_t addr) {
    asm volatile("ldmatrix.sync.aligned.m8n8.x4.trans.shared.b16 {%0,%1,%2,%3}, [%4];"
                 : "=r"(r[0]), "=r"(r[1]), "=r"(r[2]), "=r"(r[3]) : "r"(addr));
}
__device__ __forceinline__ void mma16(float* d, const uint32_t* a, uint32_t b0, uint32_t b1) {
    asm volatile(
        "mma.sync.aligned.m16n8k16.row.col.f32.f16.f16.f32 "
        "{%0,%1,%2,%3}, {%4,%5,%6,%7}, {%8,%9}, {%0,%1,%2,%3};"
        : "+f"(d[0]), "+f"(d[1]), "+f"(d[2]), "+f"(d[3])
        : "r"(a[0]), "r"(a[1]), "r"(a[2]), "r"(a[3]), "r"(b0), "r"(b1));
}

// ---------------- kernel 0: We -> fp16 ----------------
__global__ void conv_we(const float* __restrict__ We) {
    int i = blockIdx.x * blockDim.x + threadIdx.x;    // over float4 slots
    float4 v = ((const float4*)We)[i];
    uint2 u;
    u.x = packh2(v.y, v.x);
    u.y = packh2(v.w, v.z);
    *(uint2*)(We16 + (size_t)4 * i) = u;
}

// ---------------- kernel 1: gating + bucketing + x16 emit + fused tile build ----------------
__global__ void moe_gating(const float* __restrict__ x,
                           const float* __restrict__ wg,
                           const float* __restrict__ bg) {
    __shared__ float wgs[DD * NE];
    __shared__ float bgs[NE];
    __shared__ int   s_last, s_total;
    int t = threadIdx.x;
    for (int i = t; i < DD * NE; i += blockDim.x) wgs[i] = wg[i];
    if (t < NE) bgs[t] = bg[t];
    __syncthreads();

    int row = blockIdx.x * blockDim.x + t;
    const float4* xr = (const float4*)(x + (size_t)row * DD);
    const float4* wgs4 = (const float4*)wgs;

    float z[NE];
#pragma unroll
    for (int e = 0; e < NE; e++) z[e] = bgs[e];
#pragma unroll
    for (int k4 = 0; k4 < DD / 4; k4++) {
        float4 xv = xr[k4];
        const float* xc = &xv.x;
#pragma unroll
        for (int kk = 0; kk < 4; kk++) {
            float xk = xc[kk];
            int kb = (k4 * 4 + kk) * 4;
            float4 w0 = wgs4[kb + 0], w1 = wgs4[kb + 1], w2 = wgs4[kb + 2], w3 = wgs4[kb + 3];
            z[0]  += xk * w0.x; z[1]  += xk * w0.y; z[2]  += xk * w0.z; z[3]  += xk * w0.w;
            z[4]  += xk * w1.x; z[5]  += xk * w1.y; z[6]  += xk * w1.z; z[7]  += xk * w1.w;
            z[8]  += xk * w2.x; z[9]  += xk * w2.y; z[10] += xk * w2.z; z[11] += xk * w2.w;
            z[12] += xk * w3.x; z[13] += xk * w3.y; z[14] += xk * w3.z; z[15] += xk * w3.w;
        }
    }

    // emit fp16 copy of this row (x is L1-hot)
    {
        __half* xd = x16 + (size_t)row * DD;
#pragma unroll
        for (int q = 0; q < 8; q++) {
            float4 a = xr[2 * q], b = xr[2 * q + 1];
            uint4 u;
            u.x = packh2(a.y, a.x);
            u.y = packh2(a.w, a.z);
            u.z = packh2(b.y, b.x);
            u.w = packh2(b.w, b.z);
            *(uint4*)(xd + 8 * q) = u;
        }
    }

    float v0 = -1e30f, v1 = -1e30f;
    int i0 = 0, i1 = 0;
#pragma unroll
    for (int e = 0; e < NE; e++) {
        float ze = z[e];
        if (ze > v0) { v1 = v0; i1 = i0; v0 = ze; i0 = e; }
        else if (ze > v1) { v1 = ze; i1 = e; }
    }
    float s = 0.f;
#pragma unroll
    for (int e = 0; e < NE; e++) s += __expf(z[e] - v0);
    float p0 = 1.0f / s;
    float p1 = __expf(v1 - v0) / s;
    float den = p0 + p1 + 1e-6f;
    float gate0 = p0 / den, gate1 = p1 / den;

    int a, b; float ga, gb;
    if (i0 < i1) { a = i0; b = i1; ga = gate0; gb = gate1; }
    else         { a = i1; b = i0; ga = gate1; gb = gate0; }
    int p = a * NE + b;

    int pos = atomicAdd(&g_cnt[p * 32], 1);
    if (pos < CAP) {
        g_rows[p * CAP + pos]  = row;
        g_gates[p * CAP + pos] = make_float2(ga, gb);
    }

    // ---- last-block fused tile build ----
    __syncthreads();
    if (t == 0) {
        __threadfence();
        s_last = (atomicAdd(&g_done, 1) == gridDim.x - 1) ? 1 : 0;
        s_total = 0;
    }
    __syncthreads();
    if (s_last) {
        __threadfence();
        int pp = t;
        int cn = atomicAdd(&g_cnt[pp * 32], 0);
        if (cn > CAP) cn = CAP;
        int nt = (cn + BM - 1) >> 7;
        if (nt > 0) {
            int base = atomicAdd(&s_total, nt);
            for (int i = 0; i < nt; i++)
                if (base + i < MAXT) g_tiles[base + i] = make_int4(pp, i * BM, cn, 0);
        }
        g_cnt[pp * 32] = 0;
        __syncthreads();
        if (t == 0) { g_ntiles = s_total; g_done = 0; __threadfence(); }
    }
}

// ---------------- kernel 2: fp16 pair-bucket GEMM (ldmatrix + mma.sync) ----------------
__global__ __launch_bounds__(256, 2)
void moe_pair_gemm(const float* __restrict__ be,
                   float* __restrict__ y) {
    int ti = blockIdx.x;
    if (ti >= g_ntiles) return;
    int4 te = g_tiles[ti];
    int p = te.x, r0 = te.y, cn = te.z;
    int ea = p >> 4, eb = p & 15;
    int o0 = blockIdx.y * BN;
    int t = threadIdx.x, wid = t >> 5, lane = t & 31;
    int wm = wid & 3, wn = wid >> 2;
    int qid = lane >> 2, qtid = lane & 3;
    int sub = lane >> 3, lr = lane & 7;

    extern __shared__ unsigned char sm[];
    uint32_t smb = su32(sm);
    __half* as = (__half*)(sm + SM_A);
    __half* bs = (__half*)(sm + SM_B);
    float*  bA = (float*)(sm + SM_BESA);
    float*  bB = (float*)(sm + SM_BESB);
    float2* gsh = (float2*)(sm + SM_G);
    int*    rsh = (int*)(sm + SM_R);

    // metadata
    if (t < 128) {
        int idx = r0 + t;
        bool v = idx < cn;
        rsh[t] = v ? g_rows[p * CAP + idx] : -1;
        gsh[t] = v ? g_gates[p * CAP + idx] : make_float2(0.f, 0.f);
        bA[t] = be[(size_t)ea * NO + o0 + t];
        bB[t] = be[(size_t)eb * NO + o0 + t];
    }

    // ---- A fill: COALESCED gather from x16, gate folded via hmul2 ----
    // 8 lanes per row, 16B chunks; each row is 128B contiguous in x16.
    {
        int c = t & 7;                     // 16B chunk (8 halves)
        int rb = t >> 3;                   // 0..31
#pragma unroll
        for (int i = 0; i < 4; i++) {
            int r = rb + 32 * i;
            int idx = r0 + r;
            bool vld = idx < cn;
            float2 gg = vld ? g_gates[p * CAP + idx] : make_float2(0.f, 0.f);
            int row = vld ? g_rows[p * CAP + idx] : 0;
            uint4 v = *(const uint4*)(x16 + (size_t)row * DD + 8 * c);
            __half2 ga = __float2half2_rn(gg.x);
            __half2 gb = __float2half2_rn(gg.y);
            uint4 ua, ub;
            ua.x = h2m(v.x, ga); ua.y = h2m(v.y, ga); ua.z = h2m(v.z, ga); ua.w = h2m(v.w, ga);
            ub.x = h2m(v.x, gb); ub.y = h2m(v.y, gb); ub.z = h2m(v.z, gb); ub.w = h2m(v.w, gb);
            *(uint4*)(as + r * AS + 8 * c)      = ua;
            *(uint4*)(as + r * AS + 64 + 8 * c) = ub;
        }
    }

    // ---- B fill: straight 16B copies from We16 ----
    {
        const __half* Wa = We16 + ((size_t)ea * DD) * NO + o0;
        const __half* Wb = We16 + ((size_t)eb * DD) * NO + o0;
#pragma unroll
        for (int i = 0; i < 8; i++) {
            int slot = t + 256 * i;        // 0..2047
            int c8 = slot & 15;            // 16B chunk within 128-col row
            int k  = slot >> 4;            // 0..127
            const __half* src = ((k < 64) ? (Wa + (size_t)k * NO)
                                          : (Wb + (size_t)(k - 64) * NO)) + 8 * c8;
            *(uint4*)(bs + k * BS + 8 * c8) = *(const uint4*)src;
        }
    }
    __syncthreads();

    // per-thread row metadata
    float2 G[2][2]; int R[2][2];
#pragma unroll
    for (int mt = 0; mt < 2; mt++)
#pragma unroll
        for (int j = 0; j < 2; j++) {
            int m = wm * 32 + mt * 16 + j * 8 + qid;
            G[mt][j] = gsh[m];
            R[mt][j] = rsh[m];
        }

    float acc[2][8][4];
#pragma unroll
    for (int mt = 0; mt < 2; mt++)
#pragma unroll
        for (int nt = 0; nt < 8; nt++)
#pragma unroll
            for (int c = 0; c < 4; c++) acc[mt][nt][c] = 0.f;

    // ldmatrix lane addresses
    uint32_t aadr[2], badr[4];
#pragma unroll
    for (int mt = 0; mt < 2; mt++) {
        int arow = wm * 32 + mt * 16 + (sub & 1) * 8 + lr;
        int acol = (sub >> 1) * 8;
        aadr[mt] = smb + SM_A + (uint32_t)(arow * AS + acol) * 2;
    }
#pragma unroll
    for (int pr = 0; pr < 4; pr++) {
        int brow = (sub & 1) * 8 + lr;
        int bcol = wn * 64 + pr * 16 + (sub >> 1) * 8;
        badr[pr] = smb + SM_B + (uint32_t)(brow * BS + bcol) * 2;
    }

    // main loop: 8 k16-steps
#pragma unroll
    for (int ks = 0; ks < 8; ks++) {
        uint32_t a0[4], a1[4], bb[4][4];
        ldx4(a0, aadr[0] + ks * 32);
        ldx4(a1, aadr[1] + ks * 32);
#pragma unroll
        for (int pr = 0; pr < 4; pr++) ldx4t(bb[pr], badr[pr] + ks * 16 * BS * 2);
#pragma unroll
        for (int nt = 0; nt < 8; nt++) {
            uint32_t b0 = bb[nt >> 1][(nt & 1) * 2];
            uint32_t b1 = bb[nt >> 1][(nt & 1) * 2 + 1];
            mma16(acc[0][nt], a0, b0, b1);
            mma16(acc[1][nt], a1, b0, b1);
        }
    }

    // epilogue: gated bias + one store per output element
#pragma unroll
    for (int mt = 0; mt < 2; mt++) {
#pragma unroll
        for (int j = 0; j < 2; j++) {
            int row = R[mt][j];
            if (row < 0) continue;
            float2 g = G[mt][j];
            float* yp = y + (size_t)row * NO + o0;
#pragma unroll
            for (int nt = 0; nt < 8; nt++) {
                int col = wn * 64 + nt * 8 + 2 * qtid;
                float2 ba = *(float2*)(bA + col);
                float2 bb2 = *(float2*)(bB + col);
                float2 o;
                o.x = acc[mt][nt][2 * j + 0] + g.x * ba.x + g.y * bb2.x;
                o.y = acc[mt][nt][2 * j + 1] + g.x * ba.y + g.y * bb2.y;
                *(float2*)(yp + col) = o;
            }
        }
    }
}

// ---------------- launch: 3 kernels ----------------
extern "C" void kernel_launch(void* const* d_in, const int* in_sizes, int n_in,
                              void* d_out, int out_size) {
    const float* x  = (const float*)d_in[0];
    const float* wg = (const float*)d_in[1];
    const float* bg = (const float*)d_in[2];
    const float* We = (const float*)d_in[3];
    const float* be = (const float*)d_in[4];
    float* y = (float*)d_out;

    conv_we<<<(NE * DD * NO / 4) / 256, 256>>>(We);
    moe_gating<<<NB / 256, 256>>>(x, wg, bg);

    cudaFuncSetAttribute(moe_pair_gemm,
                         cudaFuncAttributeMaxDynamicSharedMemorySize, SMEM_TOTAL);
    dim3 grid(768, NO / BN, 1);
    moe_pair_gemm<<<grid, 256, SMEM_TOTAL>>>(be, y);
}